// round 6
// baseline (speedup 1.0000x reference)
#include <cuda_runtime.h>
#include <cstdint>

#define BB 64
#define TT 512
#define DD 768
#define MAXN 96
#define KMAX 79             // rel_err = 0.9^(KMAX+1) ~ 2.2e-4 (4.5x under 1e-3)
#define LOG2_DECAY (-0.15200309344504995f)  // log2(0.9)
#define CHUNK 16
#define ROW_BYTES (DD * 4)                  // 3072
#define STAGE_FLOATS (CHUNK * DD)
#define DYN_SMEM (2 * CHUNK * ROW_BYTES)    // 98304

// cross-block handshake flags (zero-init; consumer resets after use -> replay-safe)
__device__ int g_flag[BB];

__device__ __forceinline__ uint32_t smem_u32(const void* p) {
    return (uint32_t)__cvta_generic_to_shared(p);
}
__device__ __forceinline__ void mbar_init(uint32_t mb, uint32_t cnt) {
    asm volatile("mbarrier.init.shared.b64 [%0], %1;" :: "r"(mb), "r"(cnt) : "memory");
}
__device__ __forceinline__ void mbar_expect_tx(uint32_t mb, uint32_t bytes) {
    asm volatile("mbarrier.arrive.expect_tx.shared.b64 _, [%0], %1;"
                 :: "r"(mb), "r"(bytes) : "memory");
}
__device__ __forceinline__ void bulk_ld(uint32_t dst, const void* src, uint32_t bytes,
                                        uint32_t mb) {
    asm volatile("cp.async.bulk.shared::cta.global.mbarrier::complete_tx::bytes "
                 "[%0], [%1], %2, [%3];"
                 :: "r"(dst), "l"(src), "r"(bytes), "r"(mb) : "memory");
}
__device__ __forceinline__ void mbar_wait(uint32_t mb, uint32_t phase) {
    asm volatile(
        "{\n\t.reg .pred P;\n\t"
        "W_%=:\n\t"
        "mbarrier.try_wait.parity.acquire.cta.shared::cta.b64 P, [%0], %1, 0x989680;\n\t"
        "@!P bra W_%=;\n\t}"
        :: "r"(mb), "r"(phase) : "memory");
}

// Grid (BB, 2), 768 threads. One block per (batch, stream).
__global__ void __launch_bounds__(DD, 1) fused_kernel(
    const float* __restrict__ spk_hist, const float* __restrict__ spk_mask,
    const float* __restrict__ act_hist, const float* __restrict__ act_mask,
    const float* __restrict__ spk_mean, const float* __restrict__ act_mean,
    const float* __restrict__ mix_logits, float* __restrict__ out)
{
    extern __shared__ float sbuf[];   // 2 stages x 16 rows x 768 floats

    const int b = blockIdx.x, s = blockIdx.y;
    const int tid = threadIdx.x;
    const int wid = tid >> 5, lane = tid & 31;

    const float* mask = (s == 0) ? spk_mask : act_mask;
    const float* X    = (s == 0) ? spk_hist : act_hist;
    const float* mean = (s == 0) ? spk_mean : act_mean;

    __shared__ int   sidx[MAXN];
    __shared__ float swt[MAXN];
    __shared__ int   wcnt[16];
    __shared__ int   kcnt[16];
    __shared__ __align__(8) unsigned long long mbar_store[2];

    const uint32_t mb0 = smem_u32(&mbar_store[0]);
    const uint32_t mb1 = smem_u32(&mbar_store[1]);
    if (tid == 0) { mbar_init(mb0, 1); mbar_init(mb1, 1); }

    // ---- Phase 1: weights via ballot suffix-scan ----
    int m = 0;
    if (tid < TT) m = (mask[b * TT + tid] > 0.5f) ? 1 : 0;
    unsigned bal = __ballot_sync(0xFFFFFFFFu, m);
    if (lane == 0 && wid < 16) wcnt[wid] = __popc(bal);
    __syncthreads();   // also fences mbarrier init

    int after = __popc(bal & (0xFFFFFFFEu << lane));
    int total = 0;
    #pragma unroll
    for (int i = 0; i < 16; i++) {
        int c = wcnt[i];
        total += c;
        if (i > wid) after += c;
    }
    int k = after;
    int keep = (tid < TT && m && k <= KMAX) ? 1 : 0;
    float w = keep ? 0.1f * exp2f((float)k * LOG2_DECAY) : 0.0f;

    unsigned kb = __ballot_sync(0xFFFFFFFFu, keep);
    if (lane == 0 && wid < 16) kcnt[wid] = __popc(kb);
    __syncthreads();

    int pos = __popc(kb & ((1u << lane) - 1u));
    int n = 0;
    #pragma unroll
    for (int i = 0; i < 16; i++) {
        int c = kcnt[i];
        if (i < wid) pos += c;
        n += c;
    }
    if (keep) {
        sidx[pos] = tid;
        swt[pos]  = w;
    }
    __syncthreads();

    // ---- Phase 2: 2-stage cp.async.bulk pipeline, thread owns column d=tid ----
    const char* rowbase = (const char*)(X + (size_t)b * TT * DD);
    const int nch = (n + CHUNK - 1) / CHUNK;
    float acc = 0.0f;

    if (n > 0) {
        // prologue: issue chunk 0 into stage 0
        if (tid == 0) {
            int rows = (n < CHUNK) ? n : CHUNK;
            mbar_expect_tx(mb0, rows * ROW_BYTES);
            uint32_t dst = smem_u32(sbuf);
            for (int i = 0; i < rows; i++)
                bulk_ld(dst + i * ROW_BYTES,
                        rowbase + (size_t)sidx[i] * ROW_BYTES, ROW_BYTES, mb0);
        }
        for (int kc = 0; kc < nch; kc++) {
            const int st = kc & 1;
            // issue next chunk into the other stage (its prior consumers synced)
            if (tid == 0 && kc + 1 < nch) {
                int r0 = (kc + 1) * CHUNK;
                int rows = n - r0; if (rows > CHUNK) rows = CHUNK;
                uint32_t mb = (st == 0) ? mb1 : mb0;
                mbar_expect_tx(mb, rows * ROW_BYTES);
                uint32_t dst = smem_u32(sbuf + (st ^ 1) * STAGE_FLOATS);
                for (int i = 0; i < rows; i++)
                    bulk_ld(dst + i * ROW_BYTES,
                            rowbase + (size_t)sidx[r0 + i] * ROW_BYTES, ROW_BYTES, mb);
            }
            mbar_wait(st == 0 ? mb0 : mb1, (kc >> 1) & 1);

            const float* bp = sbuf + st * STAGE_FLOATS + tid;
            const int base = kc * CHUNK;
            const int rows = (n - base < CHUNK) ? (n - base) : CHUNK;
            if (rows == CHUNK) {
                float a0 = 0.f, a1 = 0.f;
                #pragma unroll
                for (int i = 0; i < CHUNK; i += 2) {
                    a0 += swt[base + i]     * bp[i * DD];
                    a1 += swt[base + i + 1] * bp[(i + 1) * DD];
                }
                acc += a0 + a1;
            } else {
                for (int i = 0; i < rows; i++)
                    acc += swt[base + i] * bp[i * DD];
            }
            __syncthreads();   // stage reusable
        }
    }

    float cval = (total > 0) ? acc : mean[(size_t)b * DD + tid];

    // softmax mix weights
    float l0 = mix_logits[0], l1 = mix_logits[1];
    float mx = fmaxf(l0, l1);
    float e0 = expf(l0 - mx), e1 = expf(l1 - mx);
    float inv = 1.0f / (e0 + e1);
    float w0m = e0 * inv, w1m = e1 * inv;

    // ---- Phase 3: publish / consume / mix ----
    if (s == 0) {
        out[(size_t)(BB + b) * DD + tid] = cval;            // c_spk
        __syncthreads();
        if (tid == 0) {
            __threadfence();
            atomicExch(&g_flag[b], 1);
        }
    } else {
        out[(size_t)(2 * BB + b) * DD + tid] = cval;        // c_act
        if (tid == 0) {
            while (atomicAdd(&g_flag[b], 0) == 0) { }
            atomicExch(&g_flag[b], 0);   // reset for next graph replay
            __threadfence();
        }
        __syncthreads();
        float cs = out[(size_t)(BB + b) * DD + tid];
        out[(size_t)b * DD + tid] = w0m * cs + w1m * cval;  // c
        if (b == 0 && tid < 2) out[3 * BB * DD + tid] = (tid == 0) ? w0m : w1m;  // w
    }
}

extern "C" void kernel_launch(void* const* d_in, const int* in_sizes, int n_in,
                              void* d_out, int out_size) {
    const float* spk_hist   = (const float*)d_in[0];
    const float* spk_mask   = (const float*)d_in[1];
    const float* act_hist   = (const float*)d_in[2];
    const float* act_mask   = (const float*)d_in[3];
    const float* spk_mean   = (const float*)d_in[4];
    const float* act_mean   = (const float*)d_in[5];
    const float* mix_logits = (const float*)d_in[6];
    float* out = (float*)d_out;

    cudaFuncSetAttribute(fused_kernel,
                         cudaFuncAttributeMaxDynamicSharedMemorySize, DYN_SMEM);
    fused_kernel<<<dim3(BB, 2), DD, DYN_SMEM>>>(spk_hist, spk_mask, act_hist, act_mask,
                                                spk_mean, act_mean, mix_logits, out);
}

// round 7
// speedup vs baseline: 1.4090x; 1.4090x over previous
#include <cuda_runtime.h>
#include <cstdint>

#define BB 64
#define TT 512
#define DD 768
#define NC (DD / 4)          // 192 float4 columns
#define NTHR 192
#define ZS 4                 // t-list split factor (blocks per (b,s))
#define MAXN 96
#define KMAX 79              // rel_err = 0.9^(KMAX+1) ~ 2.2e-4 (4.5x under 1e-3)
#define LOG2_DECAY (-0.15200309344504995f)  // log2(0.9)

// scratch (no allocations allowed)
__device__ float g_part[2 * BB * ZS * DD];
__device__ float g_ne[2 * BB];
__device__ int   g_cnt[BB];   // zero-init; finisher resets -> replay-safe

__device__ __forceinline__ void fma4(float4& a, float w, const float4& v) {
    a.x += w * v.x; a.y += w * v.y; a.z += w * v.z; a.w += w * v.w;
}

// Grid (BB, 2, ZS), 192 threads.
__global__ void __launch_bounds__(NTHR) fused_kernel(
    const float* __restrict__ spk_hist, const float* __restrict__ spk_mask,
    const float* __restrict__ act_hist, const float* __restrict__ act_mask,
    const float* __restrict__ spk_mean, const float* __restrict__ act_mean,
    const float* __restrict__ mix_logits, float* __restrict__ out)
{
    const int b = blockIdx.x, s = blockIdx.y, z = blockIdx.z;
    const int tid = threadIdx.x;
    const int wid = tid >> 5, lane = tid & 31;

    const float* mask = (s == 0) ? spk_mask : act_mask;
    const float* X    = (s == 0) ? spk_hist : act_hist;

    __shared__ unsigned bits[16], kbits[16];
    __shared__ int suf[17];    // suffix popc of mask bits (suf[w] = masked at t >= 32w)
    __shared__ int pref[17];   // prefix popc of keep bits
    __shared__ int   sidx[MAXN];
    __shared__ float swt[MAXN];
    __shared__ int s_fin;

    // ---- Phase 1: mask bitmask (3 passes of 192 threads over T=512) ----
    #pragma unroll
    for (int p = 0; p < 3; p++) {
        int t = p * NTHR + tid;
        int m = (t < TT) ? (mask[b * TT + t] > 0.5f ? 1 : 0) : 0;
        unsigned bal = __ballot_sync(0xFFFFFFFFu, m);
        int w = 6 * p + wid;
        if (lane == 0 && w < 16) bits[w] = bal;
    }
    __syncthreads();
    if (tid == 0) {
        int acc = 0;
        suf[16] = 0;
        for (int w = 15; w >= 0; w--) { acc += __popc(bits[w]); suf[w] = acc; }
    }
    __syncthreads();
    const int total = suf[0];

    // per-thread keep/weight for its <=3 t's, ballot into kbits
    int   keepf[3];
    float wt[3];
    #pragma unroll
    for (int p = 0; p < 3; p++) {
        int t = p * NTHR + tid;
        int w = 6 * p + wid;
        int m = 0, k = 0;
        if (t < TT) {
            unsigned word = bits[w];
            m = (word >> lane) & 1u;
            k = suf[w + 1] + __popc(word & (0xFFFFFFFEu << lane));
        }
        int keep = (m && k <= KMAX) ? 1 : 0;
        keepf[p] = keep;
        wt[p] = keep ? 0.1f * exp2f((float)k * LOG2_DECAY) : 0.0f;
        unsigned kb = __ballot_sync(0xFFFFFFFFu, keep);
        if (lane == 0 && w < 16) kbits[w] = kb;
    }
    __syncthreads();
    if (tid == 0) {
        int acc = 0;
        for (int w = 0; w < 16; w++) { pref[w] = acc; acc += __popc(kbits[w]); }
        pref[16] = acc;
    }
    __syncthreads();
    const int n = pref[16];

    #pragma unroll
    for (int p = 0; p < 3; p++) {
        if (keepf[p]) {
            int t = p * NTHR + tid;
            int w = 6 * p + wid;
            int pos = pref[w] + __popc(kbits[w] & ((1u << lane) - 1u));
            sidx[pos] = t;
            swt[pos]  = wt[p];
        }
    }
    if (tid == 0 && z == 0) g_ne[s * BB + b] = (total > 0) ? 1.0f : 0.0f;
    __syncthreads();

    // ---- Phase 2: weighted sum over stride-ZS slice; thread owns float4 col ----
    const float4* base = (const float4*)(X + (size_t)b * TT * DD) + tid;
    float4 acc = make_float4(0.f, 0.f, 0.f, 0.f);
    int j = z;
    for (; j + 3 * ZS < n; j += 4 * ZS) {
        int   t0 = sidx[j],          t1 = sidx[j + ZS];
        int   t2 = sidx[j + 2 * ZS], t3 = sidx[j + 3 * ZS];
        float w0 = swt[j],           w1 = swt[j + ZS];
        float w2 = swt[j + 2 * ZS],  w3 = swt[j + 3 * ZS];
        float4 v0 = base[(size_t)t0 * NC];
        float4 v1 = base[(size_t)t1 * NC];
        float4 v2 = base[(size_t)t2 * NC];
        float4 v3 = base[(size_t)t3 * NC];
        fma4(acc, w0, v0); fma4(acc, w1, v1); fma4(acc, w2, v2); fma4(acc, w3, v3);
    }
    for (; j < n; j += ZS) {
        float4 v = base[(size_t)sidx[j] * NC];
        fma4(acc, swt[j], v);
    }
    ((float4*)g_part)[((s * BB + b) * ZS + z) * NC + tid] = acc;

    // ---- Phase 3: last block per b reduces and writes outputs ----
    __threadfence();
    __syncthreads();
    if (tid == 0) {
        int old = atomicAdd(&g_cnt[b], 1);
        s_fin = (old == 2 * ZS - 1) ? 1 : 0;
    }
    __syncthreads();
    if (!s_fin) return;

    __threadfence();   // acquire: partials from other blocks
    if (tid == 0) atomicExch(&g_cnt[b], 0);   // reset for next graph replay

    float l0 = mix_logits[0], l1 = mix_logits[1];
    float mx = fmaxf(l0, l1);
    float e0 = expf(l0 - mx), e1 = expf(l1 - mx);
    float inv = 1.0f / (e0 + e1);
    float w0m = e0 * inv, w1m = e1 * inv;

    const float4* ps = (const float4*)g_part + ((0 * BB + b) * ZS) * NC + tid;
    const float4* pa = (const float4*)g_part + ((1 * BB + b) * ZS) * NC + tid;
    float4 cs = make_float4(0.f, 0.f, 0.f, 0.f);
    float4 ca = make_float4(0.f, 0.f, 0.f, 0.f);
    #pragma unroll
    for (int i = 0; i < ZS; i++) { fma4(cs, 1.0f, ps[i * NC]); fma4(ca, 1.0f, pa[i * NC]); }

    if (g_ne[b] == 0.0f)
        cs = ((const float4*)(spk_mean + (size_t)b * DD))[tid];
    if (g_ne[BB + b] == 0.0f)
        ca = ((const float4*)(act_mean + (size_t)b * DD))[tid];

    float4 cm = make_float4(w0m * cs.x + w1m * ca.x, w0m * cs.y + w1m * ca.y,
                            w0m * cs.z + w1m * ca.z, w0m * cs.w + w1m * ca.w);

    ((float4*)(out + (size_t)b * DD))[tid]            = cm;   // c
    ((float4*)(out + (size_t)(BB + b) * DD))[tid]     = cs;   // c_spk
    ((float4*)(out + (size_t)(2 * BB + b) * DD))[tid] = ca;   // c_act
    if (b == 0 && tid < 2) out[3 * BB * DD + tid] = (tid == 0) ? w0m : w1m;  // w
}

extern "C" void kernel_launch(void* const* d_in, const int* in_sizes, int n_in,
                              void* d_out, int out_size) {
    const float* spk_hist   = (const float*)d_in[0];
    const float* spk_mask   = (const float*)d_in[1];
    const float* act_hist   = (const float*)d_in[2];
    const float* act_mask   = (const float*)d_in[3];
    const float* spk_mean   = (const float*)d_in[4];
    const float* act_mean   = (const float*)d_in[5];
    const float* mix_logits = (const float*)d_in[6];
    float* out = (float*)d_out;

    fused_kernel<<<dim3(BB, 2, ZS), NTHR>>>(spk_hist, spk_mask, act_hist, act_mask,
                                            spk_mean, act_mean, mix_logits, out);
}